// round 10
// baseline (speedup 1.0000x reference)
#include <cuda_runtime.h>
#include <cstdint>

#define D_MODEL 1024
#define NUM_HEADS 16
#define HEAD_DIM 64
#define BATCH 4
#define SEQ 2048
#define MTOT (BATCH*SEQ)

// ---------------- scratch (device globals: no allocs allowed) ----------------
__device__ float g_q[(size_t)MTOT * D_MODEL];
__device__ float g_k[(size_t)MTOT * D_MODEL];
__device__ float g_v[(size_t)MTOT * D_MODEL];
__device__ float g_attn[(size_t)MTOT * D_MODEL];
__device__ float g_inr[3][(size_t)MTOT * D_MODEL];       // rounded inputs
__device__ float g_wt[4][(size_t)D_MODEL * D_MODEL];     // transposed+rounded W

// ---------------- helpers ----------------------------------------------------
__device__ __forceinline__ uint32_t f2tf32(float x) {
    uint32_t r;
    asm("cvt.rna.tf32.f32 %0, %1;" : "=r"(r) : "f"(x));
    return r;
}
__device__ __forceinline__ float rtf(float x) { return __uint_as_float(f2tf32(x)); }
__device__ __forceinline__ float ex2(float x) {
    float y;
    asm("ex2.approx.f32 %0, %1;" : "=f"(y) : "f"(x));
    return y;
}
__device__ __forceinline__ void cpa16(uint32_t dst, const void* src) {
    asm volatile("cp.async.cg.shared.global [%0], [%1], 16;" :: "r"(dst), "l"(src));
}
__device__ __forceinline__ void cpa8(uint32_t dst, const void* src) {
    asm volatile("cp.async.ca.shared.global [%0], [%1], 8;" :: "r"(dst), "l"(src));
}
__device__ __forceinline__ void cpa4(uint32_t dst, const void* src) {
    asm volatile("cp.async.ca.shared.global [%0], [%1], 4;" :: "r"(dst), "l"(src));
}
#define CPA_COMMIT() asm volatile("cp.async.commit_group;" ::: "memory")
#define CPA_WAIT0()  asm volatile("cp.async.wait_group 0;" ::: "memory")
#define CPA_WAIT1()  asm volatile("cp.async.wait_group 1;" ::: "memory")

#define LDMATRIX_X4(R0, R1, R2, R3, addr)                                       \
    asm volatile("ldmatrix.sync.aligned.m8n8.x4.shared.b16 {%0,%1,%2,%3}, [%4];" \
                 : "=r"(R0), "=r"(R1), "=r"(R2), "=r"(R3) : "r"(addr))

#define MMA_TF32(C0, C1, C2, C3, A0, A1, A2, A3, B0, B1)                        \
    asm volatile("mma.sync.aligned.m16n8k8.row.col.f32.tf32.tf32.f32 "          \
                 "{%0,%1,%2,%3},{%4,%5,%6,%7},{%8,%9},{%0,%1,%2,%3};"           \
                 : "+f"(C0), "+f"(C1), "+f"(C2), "+f"(C3)                       \
                 : "r"(A0), "r"(A1), "r"(A2), "r"(A3), "r"(B0), "r"(B1))

// ---------------- pre-pass: round inputs to tf32 -----------------------------
__global__ __launch_bounds__(256)
void round_inputs_kernel(const float* __restrict__ in, float* __restrict__ out)
{
    const int i = blockIdx.x * 256 + threadIdx.x;   // float4 index
    float4 v = ((const float4*)in)[i];
    v.x = rtf(v.x); v.y = rtf(v.y); v.z = rtf(v.z); v.w = rtf(v.w);
    ((float4*)out)[i] = v;
}

// ---------------- pre-pass: transpose + round W ------------------------------
struct WtArgs { const float* W[4]; float* Wt[4]; };

__global__ __launch_bounds__(256)
void transpose_round_kernel(WtArgs args)
{
    __shared__ float tile[32][33];
    const int z = blockIdx.z;
    const float* W = args.W[z];
    float* Wt = args.Wt[z];
    const int tx = threadIdx.x;         // 0..31
    const int ty = threadIdx.y;         // 0..7
    const int x  = blockIdx.x * 32 + tx;   // n
    const int y0 = blockIdx.y * 32;        // k
#pragma unroll
    for (int i = ty; i < 32; i += 8)
        tile[i][tx] = W[(size_t)(y0 + i) * D_MODEL + x];
    __syncthreads();
    const int xo  = blockIdx.y * 32 + tx;  // k
    const int yo0 = blockIdx.x * 32;       // n
#pragma unroll
    for (int i = ty; i < 32; i += 8)
        Wt[(size_t)(yo0 + i) * D_MODEL + xo] = rtf(tile[tx][i]);
}

// ---------------- TF32 GEMM, cp.async 3-stage pipeline -----------------------
// C = A[M,K] @ Wt[N,K]^T + bias. A and Wt are PRE-ROUNDED tf32 in gmem.
// BM=128, BN=128, BK=16. 8 warps 4(m)x2(n), warp tile 32x64.
#define GBM 128
#define GBN 128
#define GBK 16
#define SA 20
#define SW 20
#define STAGES 3
#define A_BYTES (GBM * SA * 4)           // 10240
#define STG_BYTES (GBM*SA*4 + GBN*SW*4)  // 20480
#define GEMM_SMEM (STAGES * STG_BYTES)   // 61440

struct QKVArgs {
    const float* A[3];
    const float* Wt[3];
    const float* b[3];
    float*       C[3];
};

template<bool ROUND>
__device__ __forceinline__
void gemm_cpasync_body(const float* __restrict__ A,
                       const float* __restrict__ Wt,
                       const float* __restrict__ bias,
                       float* __restrict__ C,
                       int M, int N, int K)
{
    extern __shared__ float gsm[];
    const uint32_t smem_u32 = (uint32_t)__cvta_generic_to_shared(gsm);

    const int tid  = threadIdx.x;
    const int lane = tid & 31;
    const int wid  = tid >> 5;
    const int wm   = wid >> 1;          // 0..3
    const int wn   = wid & 1;           // 0..1
    const int row0 = blockIdx.y * GBM;
    const int col0 = blockIdx.x * GBN;

    const int lj = lane >> 3;
    const int lr = lane & 7;
    uint32_t a_off[2], b_off[4];
#pragma unroll
    for (int i = 0; i < 2; ++i)
        a_off[i] = ((wm * 32 + i * 16 + lr + 8 * (lj & 1)) * SA
                    + 4 * (lj >> 1)) << 2;
#pragma unroll
    for (int t = 0; t < 4; ++t)
        b_off[t] = A_BYTES + (((wn * 64 + t * 16 + lr + 8 * (lj >> 1)) * SW
                              + 4 * (lj & 1)) << 2);

    // cp.async tile issue: 512 16B-chunks each for A and Wt; 2 per thread each
    const int cm0 = tid >> 1;              // chunk row for c=0 pairing below
    auto issue = [&](int s, int k0) {
        const uint32_t sb = smem_u32 + s * STG_BYTES;
#pragma unroll
        for (int c = 0; c < 2; ++c) {
            const int idx = (tid << 1) | c;    // 0..511
            const int m = idx >> 2;            // row 0..127
            const int q = idx & 3;             // 16B chunk in row
            cpa16(sb + m * (SA * 4) + q * 16,
                  A + (size_t)(row0 + m) * K + k0 + q * 4);
            cpa16(sb + A_BYTES + m * (SW * 4) + q * 16,
                  Wt + (size_t)(col0 + m) * K + k0 + q * 4);
        }
        CPA_COMMIT();
    };
    (void)cm0;

    float acc[2][8][4];
#pragma unroll
    for (int i = 0; i < 2; ++i)
#pragma unroll
        for (int j = 0; j < 8; ++j)
#pragma unroll
            for (int e = 0; e < 4; ++e) acc[i][j][e] = 0.f;

    issue(0, 0);
    issue(1, GBK);

    const int NIT = K / GBK;   // 64
    for (int ki = 0; ki < NIT; ++ki) {
        CPA_WAIT1();
        __syncthreads();
        if (ki + 2 < NIT) issue((ki + 2) % STAGES, (ki + 2) * GBK);
        else              CPA_COMMIT();

        const uint32_t sb = smem_u32 + (ki % STAGES) * STG_BYTES;
#pragma unroll
        for (int ks = 0; ks < GBK; ks += 8) {
            uint32_t a[2][4], bq[4][4];
            LDMATRIX_X4(a[0][0], a[0][1], a[0][2], a[0][3], sb + a_off[0] + (ks << 2));
            LDMATRIX_X4(a[1][0], a[1][1], a[1][2], a[1][3], sb + a_off[1] + (ks << 2));
#pragma unroll
            for (int t = 0; t < 4; ++t)
                LDMATRIX_X4(bq[t][0], bq[t][1], bq[t][2], bq[t][3],
                            sb + b_off[t] + (ks << 2));
#pragma unroll
            for (int i = 0; i < 2; ++i) {
#pragma unroll
                for (int t = 0; t < 4; ++t) {
                    MMA_TF32(acc[i][2*t][0], acc[i][2*t][1], acc[i][2*t][2], acc[i][2*t][3],
                             a[i][0], a[i][1], a[i][2], a[i][3], bq[t][0], bq[t][1]);
                    MMA_TF32(acc[i][2*t+1][0], acc[i][2*t+1][1], acc[i][2*t+1][2], acc[i][2*t+1][3],
                             a[i][0], a[i][1], a[i][2], a[i][3], bq[t][2], bq[t][3]);
                }
            }
        }
    }

    // epilogue
#pragma unroll
    for (int i = 0; i < 2; ++i) {
        const int r = row0 + wm * 32 + i * 16 + (lane >> 2);
#pragma unroll
        for (int j = 0; j < 8; ++j) {
            const int c = col0 + wn * 64 + j * 8 + ((lane & 3) << 1);
            const float b0 = __ldg(&bias[c]);
            const float b1 = __ldg(&bias[c + 1]);
            float2 v0, v1;
            v0.x = acc[i][j][0] + b0; v0.y = acc[i][j][1] + b1;
            v1.x = acc[i][j][2] + b0; v1.y = acc[i][j][3] + b1;
            if (ROUND) {
                v0.x = rtf(v0.x); v0.y = rtf(v0.y);
                v1.x = rtf(v1.x); v1.y = rtf(v1.y);
            }
            *(float2*)&C[(size_t)r * N + c]       = v0;
            *(float2*)&C[(size_t)(r + 8) * N + c] = v1;
        }
    }
}

__global__ __launch_bounds__(256, 2)
void qkv_gemm_kernel(QKVArgs args, int M, int N, int K)
{
    const int z = blockIdx.z;
    gemm_cpasync_body<true>(args.A[z], args.Wt[z], args.b[z], args.C[z], M, N, K);
}

__global__ __launch_bounds__(256, 2)
void out_gemm_kernel(const float* __restrict__ A, const float* __restrict__ Wt,
                     const float* __restrict__ bias, float* __restrict__ C,
                     int M, int N, int K)
{
    gemm_cpasync_body<false>(A, Wt, bias, C, M, N, K);
}

// ---------------- TF32 tensor-core flash attention (R8-proven) ---------------
// Epilogue now rounds O to tf32 (feeds the conversion-free O-projection GEMM).
#define FBR 128
#define FBC 64
#define FTILES (SEQ / FBC)

__global__ __launch_bounds__(128)
void flash_attn_tc_kernel(const float* __restrict__ Q,
                          const float* __restrict__ Km,
                          const float* __restrict__ V,
                          float* __restrict__ O)
{
    extern __shared__ uint2 fsm[];            // [2][2048] K then [2][2048] V
    uint2* kbuf[2] = { fsm,        fsm + 2048 };
    uint2* vbuf[2] = { fsm + 4096, fsm + 6144 };
    const uint32_t smem_u32 = (uint32_t)__cvta_generic_to_shared(fsm);

    const int tid  = threadIdx.x;
    const int lane = tid & 31;
    const int warp = tid >> 5;
    const int g    = lane >> 2;
    const int j    = lane & 3;

    const int q0 = blockIdx.x * FBR;
    const int bh = blockIdx.y;
    const int b  = bh >> 4;
    const int h  = bh & 15;
    const size_t base = (size_t)b * SEQ * D_MODEL + (size_t)h * HEAD_DIM;

    const float c1 = 0.18033688011112042f;  // (1/sqrt(64)) * log2(e)

    auto issue_tile = [&](int bf, int k0) {
#pragma unroll
        for (int i = 0; i < 16; ++i) {
            const int f  = tid + i * 128;
            const int kk = f >> 8;
            const int tt = (f >> 5) & 7;
            const int ln = f & 31;
            const int jj = ln & 3;
            const int gg = ln >> 2;
            cpa8(smem_u32 + (bf * 2048 + f) * 8,
                 Km + base + (size_t)(k0 + tt * 8 + gg) * D_MODEL + kk * 8 + 2 * jj);
            const float* vp = V + base + (size_t)(k0 + kk * 8 + 2 * jj) * D_MODEL
                              + tt * 8 + gg;
            const uint32_t vd = smem_u32 + (4096 + bf * 2048 + f) * 8;
            cpa4(vd,     vp);
            cpa4(vd + 4, vp + D_MODEL);
        }
        CPA_COMMIT();
    };

    uint32_t qf[2][8][4];
#pragma unroll
    for (int m = 0; m < 2; ++m) {
        const int row = q0 + warp * 32 + m * 16 + g;
        const float* qp = Q + base + (size_t)row * D_MODEL;
#pragma unroll
        for (int kk = 0; kk < 8; ++kk) {
            float2 lo = *(const float2*)&qp[kk * 8 + 2 * j];
            float2 hi = *(const float2*)&qp[(size_t)8 * D_MODEL + kk * 8 + 2 * j];
            qf[m][kk][0] = f2tf32(lo.x * c1);
            qf[m][kk][2] = f2tf32(lo.y * c1);
            qf[m][kk][1] = f2tf32(hi.x * c1);
            qf[m][kk][3] = f2tf32(hi.y * c1);
        }
    }

    float accO[2][8][4];
#pragma unroll
    for (int m = 0; m < 2; ++m)
#pragma unroll
        for (int t = 0; t < 8; ++t)
#pragma unroll
            for (int e = 0; e < 4; ++e) accO[m][t][e] = 0.f;

    float mrun[2][2] = {{-1e30f, -1e30f}, {-1e30f, -1e30f}};
    float lrun[2][2] = {{0.f, 0.f}, {0.f, 0.f}};

    issue_tile(0, 0);

    for (int ti = 0; ti < FTILES; ++ti) {
        const int cur = ti & 1;
        CPA_WAIT0();
        __syncthreads();
        if (ti + 1 < FTILES)
            issue_tile(cur ^ 1, (ti + 1) * FBC);

        const uint2* kf = kbuf[cur];
        const uint2* vf = vbuf[cur];

        float accS[2][8][4];
#pragma unroll
        for (int m = 0; m < 2; ++m)
#pragma unroll
            for (int t = 0; t < 8; ++t)
#pragma unroll
                for (int e = 0; e < 4; ++e) accS[m][t][e] = 0.f;

#pragma unroll
        for (int kk = 0; kk < 8; ++kk) {
#pragma unroll
            for (int t = 0; t < 8; ++t) {
                uint2 kb = kf[(kk * 8 + t) * 32 + lane];
#pragma unroll
                for (int m = 0; m < 2; ++m) {
                    MMA_TF32(accS[m][t][0], accS[m][t][1], accS[m][t][2], accS[m][t][3],
                             qf[m][kk][0], qf[m][kk][1], qf[m][kk][2], qf[m][kk][3],
                             kb.x, kb.y);
                }
            }
        }

#pragma unroll
        for (int m = 0; m < 2; ++m) {
#pragma unroll
            for (int hh = 0; hh < 2; ++hh) {
                const int e0 = 2 * hh;
                float lm = -1e30f;
#pragma unroll
                for (int t = 0; t < 8; ++t)
                    lm = fmaxf(lm, fmaxf(accS[m][t][e0], accS[m][t][e0 + 1]));
                lm = fmaxf(lm, __shfl_xor_sync(0xffffffffu, lm, 1));
                lm = fmaxf(lm, __shfl_xor_sync(0xffffffffu, lm, 2));
                const float mnew = fmaxf(mrun[m][hh], lm);
                const float corr = ex2(mrun[m][hh] - mnew);
                mrun[m][hh] = mnew;
                float ls = 0.f;
#pragma unroll
                for (int t = 0; t < 8; ++t) {
                    float p0 = ex2(accS[m][t][e0]     - mnew);
                    float p1 = ex2(accS[m][t][e0 + 1] - mnew);
                    accS[m][t][e0]     = p0;
                    accS[m][t][e0 + 1] = p1;
                    ls += p0 + p1;
                }
                ls += __shfl_xor_sync(0xffffffffu, ls, 1);
                ls += __shfl_xor_sync(0xffffffffu, ls, 2);
                lrun[m][hh] = lrun[m][hh] * corr + ls;
#pragma unroll
                for (int t = 0; t < 8; ++t) {
                    accO[m][t][e0]     *= corr;
                    accO[m][t][e0 + 1] *= corr;
                }
            }
        }

#pragma unroll
        for (int kk = 0; kk < 8; ++kk) {
            uint32_t pf[2][4];
#pragma unroll
            for (int m = 0; m < 2; ++m) {
                pf[m][0] = f2tf32(accS[m][kk][0]);
                pf[m][1] = f2tf32(accS[m][kk][2]);
                pf[m][2] = f2tf32(accS[m][kk][1]);
                pf[m][3] = f2tf32(accS[m][kk][3]);
            }
#pragma unroll
            for (int t = 0; t < 8; ++t) {
                uint2 vb = vf[(kk * 8 + t) * 32 + lane];
#pragma unroll
                for (int m = 0; m < 2; ++m) {
                    MMA_TF32(accO[m][t][0], accO[m][t][1], accO[m][t][2], accO[m][t][3],
                             pf[m][0], pf[m][1], pf[m][2], pf[m][3],
                             vb.x, vb.y);
                }
            }
        }
    }

#pragma unroll
    for (int m = 0; m < 2; ++m) {
        const int row = q0 + warp * 32 + m * 16 + g;
        const float inv0 = 1.f / lrun[m][0];
        const float inv1 = 1.f / lrun[m][1];
        float* op0 = O + base + (size_t)row * D_MODEL;
        float* op1 = op0 + (size_t)8 * D_MODEL;
#pragma unroll
        for (int t = 0; t < 8; ++t) {
            const int c = t * 8 + 2 * j;
            float2 v0, v1;
            v0.x = rtf(accO[m][t][0] * inv0); v0.y = rtf(accO[m][t][1] * inv0);
            v1.x = rtf(accO[m][t][2] * inv1); v1.y = rtf(accO[m][t][3] * inv1);
            *(float2*)&op0[c] = v0;
            *(float2*)&op1[c] = v1;
        }
    }
}

// ---------------- launch ----------------------------------------------------
extern "C" void kernel_launch(void* const* d_in, const int* in_sizes, int n_in,
                              void* d_out, int out_size)
{
    const float* query = (const float*)d_in[0];
    const float* key   = (const float*)d_in[1];
    const float* value = (const float*)d_in[2];
    const float* Wq    = (const float*)d_in[3];
    const float* bq    = (const float*)d_in[4];
    const float* Wk    = (const float*)d_in[5];
    const float* bk    = (const float*)d_in[6];
    const float* Wv    = (const float*)d_in[7];
    const float* bv    = (const float*)d_in[8];
    const float* Wo    = (const float*)d_in[9];
    const float* bo    = (const float*)d_in[10];
    float* out = (float*)d_out;

    float *pq, *pk, *pv, *pa, *pin, *pwt;
    cudaGetSymbolAddress((void**)&pq, g_q);
    cudaGetSymbolAddress((void**)&pk, g_k);
    cudaGetSymbolAddress((void**)&pv, g_v);
    cudaGetSymbolAddress((void**)&pa, g_attn);
    cudaGetSymbolAddress((void**)&pin, g_inr);
    cudaGetSymbolAddress((void**)&pwt, g_wt);
    float* pinr[3] = { pin, pin + (size_t)MTOT * D_MODEL, pin + 2 * (size_t)MTOT * D_MODEL };
    float* pwts[4] = { pwt, pwt + (size_t)D_MODEL * D_MODEL,
                       pwt + 2 * (size_t)D_MODEL * D_MODEL, pwt + 3 * (size_t)D_MODEL * D_MODEL };

    static bool attr_done = false;
    if (!attr_done) {
        cudaFuncSetAttribute(flash_attn_tc_kernel,
                             cudaFuncAttributeMaxDynamicSharedMemorySize, 65536);
        cudaFuncSetAttribute(qkv_gemm_kernel,
                             cudaFuncAttributeMaxDynamicSharedMemorySize, GEMM_SMEM);
        cudaFuncSetAttribute(out_gemm_kernel,
                             cudaFuncAttributeMaxDynamicSharedMemorySize, GEMM_SMEM);
        attr_done = true;
    }

    // pre-pass: round inputs, transpose+round weights
    const int n4 = MTOT * D_MODEL / 4;       // 2,097,152
    round_inputs_kernel<<<n4 / 256, 256>>>(query, pinr[0]);
    round_inputs_kernel<<<n4 / 256, 256>>>(key,   pinr[1]);
    round_inputs_kernel<<<n4 / 256, 256>>>(value, pinr[2]);

    WtArgs wargs;
    wargs.W[0] = Wq; wargs.W[1] = Wk; wargs.W[2] = Wv; wargs.W[3] = Wo;
    wargs.Wt[0] = pwts[0]; wargs.Wt[1] = pwts[1]; wargs.Wt[2] = pwts[2]; wargs.Wt[3] = pwts[3];
    dim3 tg(D_MODEL / 32, D_MODEL / 32, 4);
    transpose_round_kernel<<<tg, dim3(32, 8)>>>(wargs);

    // projections
    QKVArgs args;
    args.A[0] = pinr[0]; args.Wt[0] = pwts[0]; args.b[0] = bq; args.C[0] = pq;
    args.A[1] = pinr[1]; args.Wt[1] = pwts[1]; args.b[1] = bk; args.C[1] = pk;
    args.A[2] = pinr[2]; args.Wt[2] = pwts[2]; args.b[2] = bv; args.C[2] = pv;

    dim3 qkvg(D_MODEL / GBN, MTOT / GBM, 3);   // 8 x 64 x 3
    qkv_gemm_kernel<<<qkvg, 256, GEMM_SMEM>>>(args, MTOT, D_MODEL, D_MODEL);

    dim3 ablk(SEQ / FBR, BATCH * NUM_HEADS);   // 16 x 64
    flash_attn_tc_kernel<<<ablk, 128, 65536>>>(pq, pk, pv, pa);

    dim3 og(D_MODEL / GBN, MTOT / GBM);        // 8 x 64
    out_gemm_kernel<<<og, 256, GEMM_SMEM>>>(pa, pwts[3], bo, out, MTOT, D_MODEL, D_MODEL);
}

// round 12
// speedup vs baseline: 1.0935x; 1.0935x over previous
#include <cuda_runtime.h>
#include <cstdint>

#define D_MODEL 1024
#define NUM_HEADS 16
#define HEAD_DIM 64
#define BATCH 4
#define SEQ 2048
#define MTOT (BATCH*SEQ)

// ---------------- scratch (device globals: no allocs allowed) ----------------
__device__ float g_q[(size_t)MTOT * D_MODEL];
__device__ float g_k[(size_t)MTOT * D_MODEL];
__device__ float g_v[(size_t)MTOT * D_MODEL];
__device__ float g_attn[(size_t)MTOT * D_MODEL];

// ---------------- helpers ----------------------------------------------------
__device__ __forceinline__ uint32_t f2tf32(float x) {
    uint32_t r;
    asm("cvt.rna.tf32.f32 %0, %1;" : "=r"(r) : "f"(x));
    return r;
}
__device__ __forceinline__ float ex2(float x) {
    float y;
    asm("ex2.approx.f32 %0, %1;" : "=f"(y) : "f"(x));
    return y;
}
__device__ __forceinline__ void cpa8(uint32_t dst, const void* src) {
    asm volatile("cp.async.ca.shared.global [%0], [%1], 8;" :: "r"(dst), "l"(src));
}
__device__ __forceinline__ void cpa4(uint32_t dst, const void* src) {
    asm volatile("cp.async.ca.shared.global [%0], [%1], 4;" :: "r"(dst), "l"(src));
}
#define CPA_COMMIT() asm volatile("cp.async.commit_group;" ::: "memory")
#define CPA_WAIT0()  asm volatile("cp.async.wait_group 0;" ::: "memory")

#define LDMATRIX_X4(R0, R1, R2, R3, addr)                                       \
    asm volatile("ldmatrix.sync.aligned.m8n8.x4.shared.b16 {%0,%1,%2,%3}, [%4];" \
                 : "=r"(R0), "=r"(R1), "=r"(R2), "=r"(R3) : "r"(addr))

#define MMA_TF32(C0, C1, C2, C3, A0, A1, A2, A3, B0, B1)                        \
    asm volatile("mma.sync.aligned.m16n8k8.row.col.f32.tf32.tf32.f32 "          \
                 "{%0,%1,%2,%3},{%4,%5,%6,%7},{%8,%9},{%0,%1,%2,%3};"           \
                 : "+f"(C0), "+f"(C1), "+f"(C2), "+f"(C3)                       \
                 : "r"(A0), "r"(A1), "r"(A2), "r"(A3), "r"(B0), "r"(B1))

// ---------------- TF32 tensor-core GEMM (R9-proven) --------------------------
// BM=128, BN=128, BK=16. 8 warps 4(m)x2(n), warp tile 32x64. Single-buffered.
#define GBM 128
#define GBN 128
#define GBK 16
#define SA 20
#define SW 20

struct QKVArgs {
    const float* A[3];
    const float* W[3];
    const float* b[3];
    float*       C[3];
};

template<bool ROUND>
__device__ __forceinline__
void gemm_tf32_body(const float* __restrict__ A,
                    const float* __restrict__ W,
                    const float* __restrict__ bias,
                    float* __restrict__ C,
                    int M, int N, int K)
{
    __shared__ float As[GBM * SA];
    __shared__ float Ws[GBN * SW];

    const int tid  = threadIdx.x;
    const int lane = tid & 31;
    const int wid  = tid >> 5;
    const int wm   = wid >> 1;          // 0..3
    const int wn   = wid & 1;           // 0..1
    const int row0 = blockIdx.y * GBM;
    const int col0 = blockIdx.x * GBN;

    const int ar  = tid >> 2;
    const int akq = (tid & 3) << 2;
    const int wnx = tid & 127;
    const int wkg = (tid >> 7) << 3;    // 0 or 8

    const int lj = lane >> 3;
    const int lr = lane & 7;
    const uint32_t as_base = (uint32_t)__cvta_generic_to_shared(As);
    const uint32_t ws_base = (uint32_t)__cvta_generic_to_shared(Ws);
    uint32_t a_addr[2], b_addr[4];
#pragma unroll
    for (int i = 0; i < 2; ++i)
        a_addr[i] = as_base + (((wm * 32 + i * 16 + lr + 8 * (lj & 1)) * SA
                               + 4 * (lj >> 1)) << 2);
#pragma unroll
    for (int t = 0; t < 4; ++t)
        b_addr[t] = ws_base + (((wn * 64 + t * 16 + lr + 8 * (lj >> 1)) * SW
                               + 4 * (lj & 1)) << 2);

    float acc[2][8][4];
#pragma unroll
    for (int i = 0; i < 2; ++i)
#pragma unroll
        for (int j = 0; j < 8; ++j)
#pragma unroll
            for (int e = 0; e < 4; ++e) acc[i][j][e] = 0.f;

    const float* Ap0 = A + (size_t)(row0 + ar) * K + akq;
    const float* Ap1 = A + (size_t)(row0 + 64 + ar) * K + akq;
    const float* Wp  = W + (size_t)wkg * N + col0 + wnx;

    float4 pa0, pa1;
    float pw[8];

    pa0 = *(const float4*)Ap0;
    pa1 = *(const float4*)Ap1;
#pragma unroll
    for (int r = 0; r < 8; ++r) pw[r] = Wp[(size_t)r * N];

    {
        float4 s0, s1;
        s0.x = __uint_as_float(f2tf32(pa0.x)); s0.y = __uint_as_float(f2tf32(pa0.y));
        s0.z = __uint_as_float(f2tf32(pa0.z)); s0.w = __uint_as_float(f2tf32(pa0.w));
        s1.x = __uint_as_float(f2tf32(pa1.x)); s1.y = __uint_as_float(f2tf32(pa1.y));
        s1.z = __uint_as_float(f2tf32(pa1.z)); s1.w = __uint_as_float(f2tf32(pa1.w));
        *(float4*)&As[ar * SA + akq]        = s0;
        *(float4*)&As[(64 + ar) * SA + akq] = s1;
        float4 w0, w1;
        w0.x = __uint_as_float(f2tf32(pw[0])); w0.y = __uint_as_float(f2tf32(pw[1]));
        w0.z = __uint_as_float(f2tf32(pw[2])); w0.w = __uint_as_float(f2tf32(pw[3]));
        w1.x = __uint_as_float(f2tf32(pw[4])); w1.y = __uint_as_float(f2tf32(pw[5]));
        w1.z = __uint_as_float(f2tf32(pw[6])); w1.w = __uint_as_float(f2tf32(pw[7]));
        *(float4*)&Ws[wnx * SW + wkg]     = w0;
        *(float4*)&Ws[wnx * SW + wkg + 4] = w1;
    }
    __syncthreads();

    for (int k0 = 0; k0 < K; k0 += GBK) {
        const bool has_next = (k0 + GBK) < K;
        if (has_next) {
            pa0 = *(const float4*)(Ap0 + k0 + GBK);
            pa1 = *(const float4*)(Ap1 + k0 + GBK);
            const float* wp = Wp + (size_t)(k0 + GBK) * N;
#pragma unroll
            for (int r = 0; r < 8; ++r) pw[r] = wp[(size_t)r * N];
        }

#pragma unroll
        for (int ks = 0; ks < GBK; ks += 8) {
            uint32_t a[2][4], bq[4][4];
            LDMATRIX_X4(a[0][0], a[0][1], a[0][2], a[0][3], a_addr[0] + (ks << 2));
            LDMATRIX_X4(a[1][0], a[1][1], a[1][2], a[1][3], a_addr[1] + (ks << 2));
#pragma unroll
            for (int t = 0; t < 4; ++t)
                LDMATRIX_X4(bq[t][0], bq[t][1], bq[t][2], bq[t][3],
                            b_addr[t] + (ks << 2));
#pragma unroll
            for (int i = 0; i < 2; ++i) {
#pragma unroll
                for (int t = 0; t < 4; ++t) {
                    MMA_TF32(acc[i][2*t][0], acc[i][2*t][1], acc[i][2*t][2], acc[i][2*t][3],
                             a[i][0], a[i][1], a[i][2], a[i][3], bq[t][0], bq[t][1]);
                    MMA_TF32(acc[i][2*t+1][0], acc[i][2*t+1][1], acc[i][2*t+1][2], acc[i][2*t+1][3],
                             a[i][0], a[i][1], a[i][2], a[i][3], bq[t][2], bq[t][3]);
                }
            }
        }

        __syncthreads();
        if (has_next) {
            float4 s0, s1;
            s0.x = __uint_as_float(f2tf32(pa0.x)); s0.y = __uint_as_float(f2tf32(pa0.y));
            s0.z = __uint_as_float(f2tf32(pa0.z)); s0.w = __uint_as_float(f2tf32(pa0.w));
            s1.x = __uint_as_float(f2tf32(pa1.x)); s1.y = __uint_as_float(f2tf32(pa1.y));
            s1.z = __uint_as_float(f2tf32(pa1.z)); s1.w = __uint_as_float(f2tf32(pa1.w));
            *(float4*)&As[ar * SA + akq]        = s0;
            *(float4*)&As[(64 + ar) * SA + akq] = s1;
            float4 w0, w1;
            w0.x = __uint_as_float(f2tf32(pw[0])); w0.y = __uint_as_float(f2tf32(pw[1]));
            w0.z = __uint_as_float(f2tf32(pw[2])); w0.w = __uint_as_float(f2tf32(pw[3]));
            w1.x = __uint_as_float(f2tf32(pw[4])); w1.y = __uint_as_float(f2tf32(pw[5]));
            w1.z = __uint_as_float(f2tf32(pw[6])); w1.w = __uint_as_float(f2tf32(pw[7]));
            *(float4*)&Ws[wnx * SW + wkg]     = w0;
            *(float4*)&Ws[wnx * SW + wkg + 4] = w1;
            __syncthreads();
        }
    }

#pragma unroll
    for (int i = 0; i < 2; ++i) {
        const int r = row0 + wm * 32 + i * 16 + (lane >> 2);
#pragma unroll
        for (int j = 0; j < 8; ++j) {
            const int c = col0 + wn * 64 + j * 8 + ((lane & 3) << 1);
            const float b0 = __ldg(&bias[c]);
            const float b1 = __ldg(&bias[c + 1]);
            float2 v0, v1;
            v0.x = acc[i][j][0] + b0; v0.y = acc[i][j][1] + b1;
            v1.x = acc[i][j][2] + b0; v1.y = acc[i][j][3] + b1;
            if (ROUND) {
                v0.x = __uint_as_float(f2tf32(v0.x));
                v0.y = __uint_as_float(f2tf32(v0.y));
                v1.x = __uint_as_float(f2tf32(v1.x));
                v1.y = __uint_as_float(f2tf32(v1.y));
            }
            *(float2*)&C[(size_t)r * N + c]       = v0;
            *(float2*)&C[(size_t)(r + 8) * N + c] = v1;
        }
    }
}

__global__ __launch_bounds__(256, 2)
void qkv_gemm_kernel(QKVArgs args, int M, int N, int K)
{
    const int z = blockIdx.z;
    gemm_tf32_body<true>(args.A[z], args.W[z], args.b[z], args.C[z], M, N, K);
}

__global__ __launch_bounds__(256, 2)
void out_gemm_kernel(const float* __restrict__ A, const float* __restrict__ W,
                     const float* __restrict__ bias, float* __restrict__ C,
                     int M, int N, int K)
{
    gemm_tf32_body<false>(A, W, bias, C, M, N, K);
}

// ---------------- TF32 tensor-core flash attention ---------------------------
// 128 threads / 4 warps; warp owns 32 q-rows (2 m16 tiles). BC=64 keys/tile.
// Q frags manually spilled to smem (each thread's own slot; no syncs needed)
// so live regs fit 3 blocks/SM. K/V single-buffered; K(i+1) issued right after
// QK consumes kbuf (overlaps softmax+PV); V(i+1) after PV consumes vbuf.
#define FBR 128
#define FBC 64
#define FTILES (SEQ / FBC)
// smem: kbuf uint2[2048] (16KB) | vbuf uint2[2048] (16KB) | qbuf uint4[2048] (32KB)
#define FLASH_SMEM 65536

__global__ __launch_bounds__(128, 3)
void flash_attn_tc_kernel(const float* __restrict__ Q,
                          const float* __restrict__ Km,
                          const float* __restrict__ V,
                          float* __restrict__ O)
{
    extern __shared__ uint2 fsm[];
    const uint2* kf = fsm;                 // [2048]
    const uint2* vf = fsm + 2048;          // [2048]
    uint4* qbuf = (uint4*)(fsm + 4096);    // [2048]
    const uint32_t smem_u32 = (uint32_t)__cvta_generic_to_shared(fsm);

    const int tid  = threadIdx.x;
    const int lane = tid & 31;
    const int warp = tid >> 5;
    const int g    = lane >> 2;
    const int j    = lane & 3;

    const int q0 = blockIdx.x * FBR;
    const int bh = blockIdx.y;
    const int b  = bh >> 4;
    const int h  = bh & 15;
    const size_t base = (size_t)b * SEQ * D_MODEL + (size_t)h * HEAD_DIM;

    const float c1 = 0.18033688011112042f;  // (1/sqrt(64)) * log2(e)

    auto issue_k = [&](int k0) {
#pragma unroll
        for (int i = 0; i < 16; ++i) {
            const int f  = tid + i * 128;
            const int kk = f >> 8;
            const int tt = (f >> 5) & 7;
            const int ln = f & 31;
            const int jj = ln & 3;
            const int gg = ln >> 2;
            cpa8(smem_u32 + f * 8,
                 Km + base + (size_t)(k0 + tt * 8 + gg) * D_MODEL + kk * 8 + 2 * jj);
        }
        CPA_COMMIT();
    };
    auto issue_v = [&](int k0) {
#pragma unroll
        for (int i = 0; i < 16; ++i) {
            const int f  = tid + i * 128;
            const int kk = f >> 8;
            const int tt = (f >> 5) & 7;
            const int ln = f & 31;
            const int jj = ln & 3;
            const int gg = ln >> 2;
            const float* vp = V + base + (size_t)(k0 + kk * 8 + 2 * jj) * D_MODEL
                              + tt * 8 + gg;
            const uint32_t vd = smem_u32 + (2048 + f) * 8;
            cpa4(vd,     vp);
            cpa4(vd + 4, vp + D_MODEL);
        }
        CPA_COMMIT();
    };

    // ---- Q frags: compute once, spill to private smem slots ----
#pragma unroll
    for (int m = 0; m < 2; ++m) {
        const int row = q0 + warp * 32 + m * 16 + g;
        const float* qp = Q + base + (size_t)row * D_MODEL;
#pragma unroll
        for (int kk = 0; kk < 8; ++kk) {
            float2 lo = *(const float2*)&qp[kk * 8 + 2 * j];
            float2 hi = *(const float2*)&qp[(size_t)8 * D_MODEL + kk * 8 + 2 * j];
            uint4 qv;
            qv.x = f2tf32(lo.x * c1);
            qv.z = f2tf32(lo.y * c1);
            qv.y = f2tf32(hi.x * c1);
            qv.w = f2tf32(hi.y * c1);
            qbuf[((warp * 2 + m) * 8 + kk) * 32 + lane] = qv;
        }
    }

    float accO[2][8][4];
#pragma unroll
    for (int m = 0; m < 2; ++m)
#pragma unroll
        for (int t = 0; t < 8; ++t)
#pragma unroll
            for (int e = 0; e < 4; ++e) accO[m][t][e] = 0.f;

    float mrun[2][2] = {{-1e30f, -1e30f}, {-1e30f, -1e30f}};
    float lrun[2][2] = {{0.f, 0.f}, {0.f, 0.f}};

    issue_k(0);
    issue_v(0);

    for (int ti = 0; ti < FTILES; ++ti) {
        CPA_WAIT0();
        __syncthreads();           // K(ti) + V(ti) visible to all

        // ---- S = (Q*c1) @ K^T ----
        float accS[2][8][4];
#pragma unroll
        for (int m = 0; m < 2; ++m)
#pragma unroll
            for (int t = 0; t < 8; ++t)
#pragma unroll
                for (int e = 0; e < 4; ++e) accS[m][t][e] = 0.f;

#pragma unroll
        for (int kk = 0; kk < 8; ++kk) {
            const uint4 qm0 = qbuf[((warp * 2 + 0) * 8 + kk) * 32 + lane];
            const uint4 qm1 = qbuf[((warp * 2 + 1) * 8 + kk) * 32 + lane];
#pragma unroll
            for (int t = 0; t < 8; ++t) {
                uint2 kb = kf[(kk * 8 + t) * 32 + lane];
                MMA_TF32(accS[0][t][0], accS[0][t][1], accS[0][t][2], accS[0][t][3],
                         qm0.x, qm0.y, qm0.z, qm0.w, kb.x, kb.y);
                MMA_TF32(accS[1][t][0], accS[1][t][1], accS[1][t][2], accS[1][t][3],
                         qm1.x, qm1.y, qm1.z, qm1.w, kb.x, kb.y);
            }
        }

        __syncthreads();           // all warps done reading kbuf
        if (ti + 1 < FTILES)
            issue_k((ti + 1) * FBC);   // K prefetch overlaps softmax + PV

        // ---- online softmax (base-2) ----
#pragma unroll
        for (int m = 0; m < 2; ++m) {
#pragma unroll
            for (int hh = 0; hh < 2; ++hh) {
                const int e0 = 2 * hh;
                float lm = -1e30f;
#pragma unroll
                for (int t = 0; t < 8; ++t)
                    lm = fmaxf(lm, fmaxf(accS[m][t][e0], accS[m][t][e0 + 1]));
                lm = fmaxf(lm, __shfl_xor_sync(0xffffffffu, lm, 1));
                lm = fmaxf(lm, __shfl_xor_sync(0xffffffffu, lm, 2));
                const float mnew = fmaxf(mrun[m][hh], lm);
                const float corr = ex2(mrun[m][hh] - mnew);
                mrun[m][hh] = mnew;
                float ls = 0.f;
#pragma unroll
                for (int t = 0; t < 8; ++t) {
                    float p0 = ex2(accS[m][t][e0]     - mnew);
                    float p1 = ex2(accS[m][t][e0 + 1] - mnew);
                    accS[m][t][e0]     = p0;
                    accS[m][t][e0 + 1] = p1;
                    ls += p0 + p1;
                }
                ls += __shfl_xor_sync(0xffffffffu, ls, 1);
                ls += __shfl_xor_sync(0xffffffffu, ls, 2);
                lrun[m][hh] = lrun[m][hh] * corr + ls;
#pragma unroll
                for (int t = 0; t < 8; ++t) {
                    accO[m][t][e0]     *= corr;
                    accO[m][t][e0 + 1] *= corr;
                }
            }
        }

        // ---- O += P @ V  (P A-frag = S C-frag rename) ----
#pragma unroll
        for (int kk = 0; kk < 8; ++kk) {
            uint32_t pf[2][4];
#pragma unroll
            for (int m = 0; m < 2; ++m) {
                pf[m][0] = f2tf32(accS[m][kk][0]);
                pf[m][1] = f2tf32(accS[m][kk][2]);
                pf[m][2] = f2tf32(accS[m][kk][1]);
                pf[m][3] = f2tf32(accS[m][kk][3]);
            }
#pragma unroll
            for (int t = 0; t < 8; ++t) {
                uint2 vb = vf[(kk * 8 + t) * 32 + lane];
#pragma unroll
                for (int m = 0; m < 2; ++m) {
                    MMA_TF32(accO[m][t][0], accO[m][t][1], accO[m][t][2], accO[m][t][3],
                             pf[m][0], pf[m][1], pf[m][2], pf[m][3],
                             vb.x, vb.y);
                }
            }
        }

        __syncthreads();           // all warps done reading vbuf
        if (ti + 1 < FTILES)
            issue_v((ti + 1) * FBC);
    }

    // ---- epilogue ----
#pragma unroll
    for (int m = 0; m < 2; ++m) {
        const int row = q0 + warp * 32 + m * 16 + g;
        const float inv0 = 1.f / lrun[m][0];
        const float inv1 = 1.f / lrun[m][1];
        float* op0 = O + base + (size_t)row * D_MODEL;
        float* op1 = op0 + (size_t)8 * D_MODEL;
#pragma unroll
        for (int t = 0; t < 8; ++t) {
            const int c = t * 8 + 2 * j;
            float2 v0, v1;
            v0.x = accO[m][t][0] * inv0; v0.y = accO[m][t][1] * inv0;
            v1.x = accO[m][t][2] * inv1; v1.y = accO[m][t][3] * inv1;
            *(float2*)&op0[c] = v0;
            *(float2*)&op1[c] = v1;
        }
    }
}

// ---------------- launch ----------------------------------------------------
extern "C" void kernel_launch(void* const* d_in, const int* in_sizes, int n_in,
                              void* d_out, int out_size)
{
    const float* query = (const float*)d_in[0];
    const float* key   = (const float*)d_in[1];
    const float* value = (const float*)d_in[2];
    const float* Wq    = (const float*)d_in[3];
    const float* bq    = (const float*)d_in[4];
    const float* Wk    = (const float*)d_in[5];
    const float* bk    = (const float*)d_in[6];
    const float* Wv    = (const float*)d_in[7];
    const float* bv    = (const float*)d_in[8];
    const float* Wo    = (const float*)d_in[9];
    const float* bo    = (const float*)d_in[10];
    float* out = (float*)d_out;

    float *pq, *pk, *pv, *pa;
    cudaGetSymbolAddress((void**)&pq, g_q);
    cudaGetSymbolAddress((void**)&pk, g_k);
    cudaGetSymbolAddress((void**)&pv, g_v);
    cudaGetSymbolAddress((void**)&pa, g_attn);

    static bool attr_done = false;
    if (!attr_done) {
        cudaFuncSetAttribute(flash_attn_tc_kernel,
                             cudaFuncAttributeMaxDynamicSharedMemorySize, FLASH_SMEM);
        attr_done = true;
    }

    QKVArgs args;
    args.A[0] = query; args.W[0] = Wq; args.b[0] = bq; args.C[0] = pq;
    args.A[1] = key;   args.W[1] = Wk; args.b[1] = bk; args.C[1] = pk;
    args.A[2] = value; args.W[2] = Wv; args.b[2] = bv; args.C[2] = pv;

    dim3 qkvg(D_MODEL / GBN, MTOT / GBM, 3);   // 8 x 64 x 3
    qkv_gemm_kernel<<<qkvg, 256>>>(args, MTOT, D_MODEL, D_MODEL);

    dim3 ablk(SEQ / FBR, BATCH * NUM_HEADS);   // 16 x 64
    flash_attn_tc_kernel<<<ablk, 128, FLASH_SMEM>>>(pq, pk, pv, pa);

    dim3 og(D_MODEL / GBN, MTOT / GBM);        // 8 x 64
    out_gemm_kernel<<<og, 256>>>(pa, Wo, bo, out, MTOT, D_MODEL, D_MODEL);
}

// round 14
// speedup vs baseline: 1.6718x; 1.5288x over previous
#include <cuda_runtime.h>
#include <cuda_fp16.h>
#include <cstdint>

#define D_MODEL 1024
#define NUM_HEADS 16
#define HEAD_DIM 64
#define BATCH 4
#define SEQ 2048
#define MTOT (BATCH*SEQ)

// ---------------- scratch (device globals: no allocs allowed) ----------------
__device__ __half g_q[(size_t)MTOT * D_MODEL];     // fp16, pre-scaled by c1
__device__ __half g_k[(size_t)MTOT * D_MODEL];     // fp16
__device__ __half g_v[(size_t)MTOT * D_MODEL];     // fp16
__device__ __half g_attn[(size_t)MTOT * D_MODEL];  // fp16

// ---------------- helpers ----------------------------------------------------
__device__ __forceinline__ uint32_t h2pack(float lo, float hi) {
    __half2 h = __floats2half2_rn(lo, hi);     // .x = lo, .y = hi
    return *reinterpret_cast<uint32_t*>(&h);
}
__device__ __forceinline__ float ex2(float x) {
    float y;
    asm("ex2.approx.f32 %0, %1;" : "=f"(y) : "f"(x));
    return y;
}
__device__ __forceinline__ void cpa16(uint32_t dst, const void* src) {
    asm volatile("cp.async.cg.shared.global [%0], [%1], 16;" :: "r"(dst), "l"(src));
}
#define CPA_COMMIT() asm volatile("cp.async.commit_group;" ::: "memory")
#define CPA_WAIT0()  asm volatile("cp.async.wait_group 0;" ::: "memory")

#define LDMATRIX_X4(R0, R1, R2, R3, addr)                                       \
    asm volatile("ldmatrix.sync.aligned.m8n8.x4.shared.b16 {%0,%1,%2,%3}, [%4];" \
                 : "=r"(R0), "=r"(R1), "=r"(R2), "=r"(R3) : "r"(addr))
#define LDMATRIX_X4_TRANS(R0, R1, R2, R3, addr)                                 \
    asm volatile("ldmatrix.sync.aligned.m8n8.x4.trans.shared.b16 {%0,%1,%2,%3}, [%4];" \
                 : "=r"(R0), "=r"(R1), "=r"(R2), "=r"(R3) : "r"(addr))

// D = A(m16k16,f16) @ B(k16n8,f16) + D, f32 accum
#define MMA_F16(C0, C1, C2, C3, A0, A1, A2, A3, B0, B1)                         \
    asm volatile("mma.sync.aligned.m16n8k16.row.col.f32.f16.f16.f32 "           \
                 "{%0,%1,%2,%3},{%4,%5,%6,%7},{%8,%9},{%0,%1,%2,%3};"           \
                 : "+f"(C0), "+f"(C1), "+f"(C2), "+f"(C3)                       \
                 : "r"(A0), "r"(A1), "r"(A2), "r"(A3), "r"(B0), "r"(B1))

// ---------------- FP16 tensor-core GEMM --------------------------------------
// C = A[M,K] @ W[K,N] + bias.  BM=128, BN=128, BK=16 (one k16 MMA step/iter).
// 8 warps 4(m)x2(n), warp tile 32x64. smem rows: 16 halfs data, stride 24 halfs
// (48B) -> ldmatrix row addresses hit 8 distinct 16B bank-groups.
#define GBM 128
#define GBN 128
#define GBK 16
#define SH 24

struct QKVArgs {
    const float* A[3];
    const float* b[3];
    const float* W[3];
    __half*      C[3];
    float        scale[3];
};

// AHALF: A operand is fp16 in gmem.  CFLOAT: output f32 (else fp16*oscale).
template<bool AHALF, bool CFLOAT>
__device__ __forceinline__
void gemm_f16_body(const void* __restrict__ Ain,
                   const float* __restrict__ W,
                   const float* __restrict__ bias,
                   void* __restrict__ Cout,
                   int M, int N, int K, float oscale)
{
    __shared__ __half As[GBM * SH];
    __shared__ __half Ws[GBN * SH];

    const int tid  = threadIdx.x;
    const int lane = tid & 31;
    const int wid  = tid >> 5;
    const int wm   = wid >> 1;          // 0..3
    const int wn   = wid & 1;           // 0..1
    const int row0 = blockIdx.y * GBM;
    const int col0 = blockIdx.x * GBN;

    const int ar  = tid >> 2;           // 0..63  (rows ar, ar+64)
    const int akq = (tid & 3) << 2;     // 0,4,8,12 (k offset, 4 elems)
    const int wnx = tid & 127;          // W: n index
    const int wkg = (tid >> 7) << 3;    // W: k rows 0..7 or 8..15

    const int lj = lane >> 3;
    const int lr = lane & 7;
    const uint32_t as_base = (uint32_t)__cvta_generic_to_shared(As);
    const uint32_t ws_base = (uint32_t)__cvta_generic_to_shared(Ws);
    uint32_t a_addr[2], b_addr[4];
#pragma unroll
    for (int i = 0; i < 2; ++i)
        a_addr[i] = as_base + (wm * 32 + i * 16 + lr + 8 * (lj & 1)) * (SH * 2)
                    + (lj >> 1) * 16;
#pragma unroll
    for (int t = 0; t < 4; ++t)
        b_addr[t] = ws_base + (wn * 64 + t * 16 + lr + 8 * (lj & 1)) * (SH * 2)
                    + (lj >> 1) * 16;

    float acc[2][8][4];
#pragma unroll
    for (int i = 0; i < 2; ++i)
#pragma unroll
        for (int j = 0; j < 8; ++j)
#pragma unroll
            for (int e = 0; e < 4; ++e) acc[i][j][e] = 0.f;

    const float*  Af = (const float*)Ain;
    const __half* Ah = (const __half*)Ain;
    const float*  Wp = W + (size_t)wkg * N + col0 + wnx;

    uint2 sa0, sa1;     // staged A halfs (4 each)
    float pw[8];

    // ---- load tile 0 ----
    if (AHALF) {
        sa0 = *(const uint2*)&Ah[(size_t)(row0 + ar) * K + akq];
        sa1 = *(const uint2*)&Ah[(size_t)(row0 + 64 + ar) * K + akq];
    } else {
        float4 a0 = *(const float4*)&Af[(size_t)(row0 + ar) * K + akq];
        float4 a1 = *(const float4*)&Af[(size_t)(row0 + 64 + ar) * K + akq];
        sa0 = make_uint2(h2pack(a0.x, a0.y), h2pack(a0.z, a0.w));
        sa1 = make_uint2(h2pack(a1.x, a1.y), h2pack(a1.z, a1.w));
    }
#pragma unroll
    for (int r = 0; r < 8; ++r) pw[r] = Wp[(size_t)r * N];

    *(uint2*)&As[ar * SH + akq]        = sa0;
    *(uint2*)&As[(64 + ar) * SH + akq] = sa1;
    {
        uint4 sw = make_uint4(h2pack(pw[0], pw[1]), h2pack(pw[2], pw[3]),
                              h2pack(pw[4], pw[5]), h2pack(pw[6], pw[7]));
        *(uint4*)&Ws[wnx * SH + wkg] = sw;
    }
    __syncthreads();

    for (int k0 = 0; k0 < K; k0 += GBK) {
        const bool has_next = (k0 + GBK) < K;
        if (has_next) {
            if (AHALF) {
                sa0 = *(const uint2*)&Ah[(size_t)(row0 + ar) * K + k0 + GBK + akq];
                sa1 = *(const uint2*)&Ah[(size_t)(row0 + 64 + ar) * K + k0 + GBK + akq];
            } else {
                float4 a0 = *(const float4*)&Af[(size_t)(row0 + ar) * K + k0 + GBK + akq];
                float4 a1 = *(const float4*)&Af[(size_t)(row0 + 64 + ar) * K + k0 + GBK + akq];
                sa0 = make_uint2(h2pack(a0.x, a0.y), h2pack(a0.z, a0.w));
                sa1 = make_uint2(h2pack(a1.x, a1.y), h2pack(a1.z, a1.w));
            }
            const float* wp = Wp + (size_t)(k0 + GBK) * N;
#pragma unroll
            for (int r = 0; r < 8; ++r) pw[r] = wp[(size_t)r * N];
        }

        // ---- MMA on current tile: one k16 step ----
        {
            uint32_t a[2][4], bq[4][4];
            LDMATRIX_X4(a[0][0], a[0][1], a[0][2], a[0][3], a_addr[0]);
            LDMATRIX_X4(a[1][0], a[1][1], a[1][2], a[1][3], a_addr[1]);
#pragma unroll
            for (int t = 0; t < 4; ++t)
                LDMATRIX_X4(bq[t][0], bq[t][1], bq[t][2], bq[t][3], b_addr[t]);
            // n16 group t: low n8 frag = (r0, r2), high n8 frag = (r1, r3)
#pragma unroll
            for (int i = 0; i < 2; ++i) {
#pragma unroll
                for (int t = 0; t < 4; ++t) {
                    MMA_F16(acc[i][2*t][0], acc[i][2*t][1], acc[i][2*t][2], acc[i][2*t][3],
                            a[i][0], a[i][1], a[i][2], a[i][3], bq[t][0], bq[t][2]);
                    MMA_F16(acc[i][2*t+1][0], acc[i][2*t+1][1], acc[i][2*t+1][2], acc[i][2*t+1][3],
                            a[i][0], a[i][1], a[i][2], a[i][3], bq[t][1], bq[t][3]);
                }
            }
        }

        __syncthreads();
        if (has_next) {
            *(uint2*)&As[ar * SH + akq]        = sa0;
            *(uint2*)&As[(64 + ar) * SH + akq] = sa1;
            uint4 sw = make_uint4(h2pack(pw[0], pw[1]), h2pack(pw[2], pw[3]),
                                  h2pack(pw[4], pw[5]), h2pack(pw[6], pw[7]));
            *(uint4*)&Ws[wnx * SH + wkg] = sw;
            __syncthreads();
        }
    }

    // ---- epilogue ----
#pragma unroll
    for (int i = 0; i < 2; ++i) {
        const int r = row0 + wm * 32 + i * 16 + (lane >> 2);
#pragma unroll
        for (int jn = 0; jn < 8; ++jn) {
            const int c = col0 + wn * 64 + jn * 8 + ((lane & 3) << 1);
            const float b0 = __ldg(&bias[c]);
            const float b1 = __ldg(&bias[c + 1]);
            float v00 = acc[i][jn][0] + b0, v01 = acc[i][jn][1] + b1;
            float v10 = acc[i][jn][2] + b0, v11 = acc[i][jn][3] + b1;
            if (CFLOAT) {
                float* Cf = (float*)Cout;
                *(float2*)&Cf[(size_t)r * N + c]       = make_float2(v00, v01);
                *(float2*)&Cf[(size_t)(r + 8) * N + c] = make_float2(v10, v11);
            } else {
                __half* Ch = (__half*)Cout;
                *(uint32_t*)&Ch[(size_t)r * N + c]       = h2pack(v00 * oscale, v01 * oscale);
                *(uint32_t*)&Ch[(size_t)(r + 8) * N + c] = h2pack(v10 * oscale, v11 * oscale);
            }
        }
    }
}

__global__ __launch_bounds__(256, 2)
void qkv_gemm_kernel(QKVArgs args, int M, int N, int K)
{
    const int z = blockIdx.z;
    gemm_f16_body<false, false>(args.A[z], args.W[z], args.b[z], args.C[z],
                                M, N, K, args.scale[z]);
}

__global__ __launch_bounds__(256, 2)
void out_gemm_kernel(const __half* __restrict__ A, const float* __restrict__ W,
                     const float* __restrict__ bias, float* __restrict__ C,
                     int M, int N, int K)
{
    gemm_f16_body<true, true>(A, W, bias, C, M, N, K, 1.f);
}

// ---------------- FP16 tensor-core flash attention ---------------------------
// 128 threads / 4 warps; warp owns 32 q-rows (2 m16 tiles). BC=64 keys/tile.
// Q/K/V already fp16 in gmem (Q pre-scaled by c1). K and V tiles stored in
// NATURAL [token][d] layout (64 rows x 128B, stride 144B -> conflict-free
// ldmatrix). K consumed via ldmatrix.x4 (B k=d), V via ldmatrix.x4.trans
// (B k=keys). S->P = direct half2 pack (no permutation). K+V double-buffered,
// one cp.async commit + one __syncthreads per tile. Q spilled to smem.
#define FBR 128
#define FBC 64
#define FTILES (SEQ / FBC)
#define KVSTRIDE 144                      // bytes per token row in smem
#define KVBYTES  (64 * KVSTRIDE)          // 9216 per tile buffer
#define OFF_K0 0
#define OFF_K1 KVBYTES
#define OFF_V0 (2 * KVBYTES)
#define OFF_V1 (3 * KVBYTES)
#define OFF_Q  (4 * KVBYTES)              // 36864
#define FLASH_SMEM (OFF_Q + 16384)        // 53248

__global__ __launch_bounds__(128, 3)
void flash_attn_f16_kernel(const __half* __restrict__ Q,
                           const __half* __restrict__ Km,
                           const __half* __restrict__ V,
                           __half* __restrict__ O)
{
    extern __shared__ char fsm[];
    const uint32_t smem_u32 = (uint32_t)__cvta_generic_to_shared(fsm);
    uint4* qb = (uint4*)(fsm + OFF_Q);

    const int tid  = threadIdx.x;
    const int lane = tid & 31;
    const int warp = tid >> 5;
    const int g    = lane >> 2;
    const int j    = lane & 3;
    const int lj   = lane >> 3;
    const int lr   = lane & 7;

    const int q0 = blockIdx.x * FBR;
    const int bh = blockIdx.y;
    const int b  = bh >> 4;
    const int h  = bh & 15;
    const size_t base = (size_t)b * SEQ * D_MODEL + (size_t)h * HEAD_DIM;

    // loader: K and V tiles, 4 cpa16 each per thread, one commit
    auto issue_tile = [&](int bf, int k0) {
        const uint32_t kb = smem_u32 + (bf ? OFF_K1 : OFF_K0);
        const uint32_t vb = smem_u32 + (bf ? OFF_V1 : OFF_V0);
#pragma unroll
        for (int i = 0; i < 4; ++i) {
            const int f   = tid + i * 128;    // 0..511
            const int row = f >> 3;           // token 0..63
            const int ch  = f & 7;            // 16B chunk (8 halfs)
            const size_t src = base + (size_t)(k0 + row) * D_MODEL + ch * 8;
            cpa16(kb + row * KVSTRIDE + ch * 16, Km + src);
            cpa16(vb + row * KVSTRIDE + ch * 16, V + src);
        }
        CPA_COMMIT();
    };

    // ldmatrix lane-address offsets (within a tile buffer)
    uint32_t koff[4], voff[4];
#pragma unroll
    for (int tp = 0; tp < 4; ++tp) {
        koff[tp] = (tp * 16 + lr + 8 * (lj & 1)) * KVSTRIDE + (lj >> 1) * 16;
        voff[tp] = (lr + 8 * (lj & 1)) * KVSTRIDE + tp * 32 + (lj >> 1) * 16;
    }

    // ---- Q frags -> smem spill (each thread's own slot) ----
#pragma unroll
    for (int m = 0; m < 2; ++m) {
        const int row = q0 + warp * 32 + m * 16 + g;
        const __half* qp  = Q + base + (size_t)row * D_MODEL;
        const __half* qp8 = qp + (size_t)8 * D_MODEL;
#pragma unroll
        for (int kk = 0; kk < 4; ++kk) {
            uint4 qv;
            qv.x = *(const uint32_t*)&qp [16 * kk + 2 * j];      // (g,   2j..)
            qv.y = *(const uint32_t*)&qp8[16 * kk + 2 * j];      // (g+8, 2j..)
            qv.z = *(const uint32_t*)&qp [16 * kk + 2 * j + 8];  // (g,   2j+8..)
            qv.w = *(const uint32_t*)&qp8[16 * kk + 2 * j + 8];  // (g+8, 2j+8..)
            qb[((warp * 2 + m) * 4 + kk) * 32 + lane] = qv;
        }
    }

    float accO[2][8][4];
#pragma unroll
    for (int m = 0; m < 2; ++m)
#pragma unroll
        for (int t = 0; t < 8; ++t)
#pragma unroll
            for (int e = 0; e < 4; ++e) accO[m][t][e] = 0.f;

    float mrun[2][2] = {{-1e30f, -1e30f}, {-1e30f, -1e30f}};
    float lrun[2][2] = {{0.f, 0.f}, {0.f, 0.f}};

    issue_tile(0, 0);

    for (int ti = 0; ti < FTILES; ++ti) {
        const int bf = ti & 1;
        CPA_WAIT0();
        __syncthreads();          // tile(ti) visible; everyone done with tile(ti-1) bufs
        if (ti + 1 < FTILES)
            issue_tile(bf ^ 1, (ti + 1) * FBC);

        const uint32_t kb = smem_u32 + (bf ? OFF_K1 : OFF_K0);
        const uint32_t vb = smem_u32 + (bf ? OFF_V1 : OFF_V0);

        // ---- S = Q @ K^T (Q pre-scaled by c1; base-2 softmax later) ----
        float accS[2][8][4];
#pragma unroll
        for (int m = 0; m < 2; ++m)
#pragma unroll
            for (int t = 0; t < 8; ++t)
#pragma unroll
                for (int e = 0; e < 4; ++e) accS[m][t][e] = 0.f;

#pragma unroll
        for (int kk = 0; kk < 4; ++kk) {
            const uint4 qm0 = qb[((warp * 2 + 0) * 4 + kk) * 32 + lane];
            const uint4 qm1 = qb[((warp * 2 + 1) * 4 + kk) * 32 + lane];
#pragma unroll
            for (int tp = 0; tp < 4; ++tp) {
                uint32_t k0r, k1r, k2r, k3r;
                LDMATRIX_X4(k0r, k1r, k2r, k3r, kb + koff[tp] + kk * 32);
                // keys tp*16+0..7 -> frag (k0r,k2r) = t 2tp ; +8..15 -> (k1r,k3r)
                MMA_F16(accS[0][2*tp][0], accS[0][2*tp][1], accS[0][2*tp][2], accS[0][2*tp][3],
                        qm0.x, qm0.y, qm0.z, qm0.w, k0r, k2r);
                MMA_F16(accS[0][2*tp+1][0], accS[0][2*tp+1][1], accS[0][2*tp+1][2], accS[0][2*tp+1][3],
                        qm0.x, qm0.y, qm0.z, qm0.w, k1r, k3r);
                MMA_F16(accS[1][2*tp][0], accS[1][2*tp][1], accS[1][2*tp][2], accS[1][2*tp][3],
                        qm1.x, qm1.y, qm1.z, qm1.w, k0r, k2r);
                MMA_F16(accS[1][2*tp+1][0], accS[1][2*tp+1][1], accS[1][2*tp+1][2], accS[1][2*tp+1][3],
                        qm1.x, qm1.y, qm1.z, qm1.w, k1r, k3r);
            }
        }

        // ---- online softmax (base-2) ----
#pragma unroll
        for (int m = 0; m < 2; ++m) {
#pragma unroll
            for (int hh = 0; hh < 2; ++hh) {
                const int e0 = 2 * hh;
                float lm = -1e30f;
#pragma unroll
                for (int t = 0; t < 8; ++t)
                    lm = fmaxf(lm, fmaxf(accS[m][t][e0], accS[m][t][e0 + 1]));
                lm = fmaxf(lm, __shfl_xor_sync(0xffffffffu, lm, 1));
                lm = fmaxf(lm, __shfl_xor_sync(0xffffffffu, lm, 2));
                const float mnew = fmaxf(mrun[m][hh], lm);
                const float corr = ex2(mrun[m][hh] - mnew);
                mrun[m][hh] = mnew;
                float ls = 0.f;
#pragma unroll
                for (int t = 0; t < 8; ++t) {
                    float p0 = ex2(accS[m][t][e0]     - mnew);
                    float p1 = ex2(accS[m][t][e0 + 1] - mnew);
                    accS[m][t][e0]     = p0;
                    accS[m][t][e0 + 1] = p1;
                    ls += p0 + p1;
                }
                ls += __shfl_xor_sync(0xffffffffu, ls, 1);
                ls += __shfl_xor_sync(0xffffffffu, ls, 2);
                lrun[m][hh] = lrun[m][hh] * corr + ls;
#pragma unroll
                for (int t = 0; t < 8; ++t) {
                    accO[m][t][e0]     *= corr;
                    accO[m][t][e0 + 1] *= corr;
                }
            }
        }

        // ---- O += P @ V  (P A-frag = half2 packs of S C-frag) ----
#pragma unroll
        for (int kk = 0; kk < 4; ++kk) {
            uint32_t pf[2][4];
#pragma unroll
            for (int m = 0; m < 2; ++m) {
                pf[m][0] = h2pack(accS[m][2*kk][0],   accS[m][2*kk][1]);    // (g, keys 2j..)
                pf[m][1] = h2pack(accS[m][2*kk][2],   accS[m][2*kk][3]);    // (g+8, ...)
                pf[m][2] = h2pack(accS[m][2*kk+1][0], accS[m][2*kk+1][1]);  // (g, keys 2j+8..)
                pf[m][3] = h2pack(accS[m][2*kk+1][2], accS[m][2*kk+1][3]);  // (g+8, ...)
            }
#pragma unroll
            for (int tp = 0; tp < 4; ++tp) {
                uint32_t v0r, v1r, v2r, v3r;
                LDMATRIX_X4_TRANS(v0r, v1r, v2r, v3r,
                                  vb + voff[tp] + kk * (16 * KVSTRIDE));
                // d-block 2tp: frag (v0r, v1r); d-block 2tp+1: (v2r, v3r)
#pragma unroll
                for (int m = 0; m < 2; ++m) {
                    MMA_F16(accO[m][2*tp][0], accO[m][2*tp][1], accO[m][2*tp][2], accO[m][2*tp][3],
                            pf[m][0], pf[m][1], pf[m][2], pf[m][3], v0r, v1r);
                    MMA_F16(accO[m][2*tp+1][0], accO[m][2*tp+1][1], accO[m][2*tp+1][2], accO[m][2*tp+1][3],
                            pf[m][0], pf[m][1], pf[m][2], pf[m][3], v2r, v3r);
                }
            }
        }
    }

    // ---- epilogue: O /= l, write fp16 (feeds O-projection) ----
#pragma unroll
    for (int m = 0; m < 2; ++m) {
        const int row = q0 + warp * 32 + m * 16 + g;
        const float inv0 = 1.f / lrun[m][0];
        const float inv1 = 1.f / lrun[m][1];
        __half* op0 = O + base + (size_t)row * D_MODEL;
        __half* op1 = op0 + (size_t)8 * D_MODEL;
#pragma unroll
        for (int t = 0; t < 8; ++t) {
            const int c = t * 8 + 2 * j;
            *(uint32_t*)&op0[c] = h2pack(accO[m][t][0] * inv0, accO[m][t][1] * inv0);
            *(uint32_t*)&op1[c] = h2pack(accO[m][t][2] * inv1, accO[m][t][3] * inv1);
        }
    }
}

// ---------------- launch ----------------------------------------------------
extern "C" void kernel_launch(void* const* d_in, const int* in_sizes, int n_in,
                              void* d_out, int out_size)
{
    const float* query = (const float*)d_in[0];
    const float* key   = (const float*)d_in[1];
    const float* value = (const float*)d_in[2];
    const float* Wq    = (const float*)d_in[3];
    const float* bq    = (const float*)d_in[4];
    const float* Wk    = (const float*)d_in[5];
    const float* bk    = (const float*)d_in[6];
    const float* Wv    = (const float*)d_in[7];
    const float* bv    = (const float*)d_in[8];
    const float* Wo    = (const float*)d_in[9];
    const float* bo    = (const float*)d_in[10];
    float* out = (float*)d_out;

    __half *pq, *pk, *pv, *pa;
    cudaGetSymbolAddress((void**)&pq, g_q);
    cudaGetSymbolAddress((void**)&pk, g_k);
    cudaGetSymbolAddress((void**)&pv, g_v);
    cudaGetSymbolAddress((void**)&pa, g_attn);

    static bool attr_done = false;
    if (!attr_done) {
        cudaFuncSetAttribute(flash_attn_f16_kernel,
                             cudaFuncAttributeMaxDynamicSharedMemorySize, FLASH_SMEM);
        attr_done = true;
    }

    const float c1 = 0.18033688011112042f;  // (1/sqrt(64)) * log2(e), folded into Q

    QKVArgs args;
    args.A[0] = query; args.W[0] = Wq; args.b[0] = bq; args.C[0] = pq; args.scale[0] = c1;
    args.A[1] = key;   args.W[1] = Wk; args.b[1] = bk; args.C[1] = pk; args.scale[1] = 1.f;
    args.A[2] = value; args.W[2] = Wv; args.b[2] = bv; args.C[2] = pv; args.scale[2] = 1.f;

    dim3 qkvg(D_MODEL / GBN, MTOT / GBM, 3);   // 8 x 64 x 3
    qkv_gemm_kernel<<<qkvg, 256>>>(args, MTOT, D_MODEL, D_MODEL);

    dim3 ablk(SEQ / FBR, BATCH * NUM_HEADS);   // 16 x 64
    flash_attn_f16_kernel<<<ablk, 128, FLASH_SMEM>>>(pq, pk, pv, pa);

    dim3 og(D_MODEL / GBN, MTOT / GBM);        // 8 x 64
    out_gemm_kernel<<<og, 256>>>(pa, Wo, bo, out, MTOT, D_MODEL, D_MODEL);
}